// round 1
// baseline (speedup 1.0000x reference)
#include <cuda_runtime.h>
#include <math.h>

#define BATCH 16
#define CDIM  512
#define ICDIM 256
#define NPIX  4096
#define SLEN  110

// -------- scratch (static device globals; no runtime allocation) --------
__device__ float g_yconv [(size_t)BATCH * CDIM  * NPIX];   // theta-conv rows 0..255, g-conv rows 256..511
__device__ float g_xphi  [(size_t)BATCH * ICDIM * NPIX];
__device__ float g_logits[(size_t)BATCH * SLEN  * NPIX];   // [b, s, n]; normalized in place to probs
__device__ float g_agg   [(size_t)BATCH * ICDIM * NPIX];
__device__ float g_theta [(size_t)BATCH * SLEN  * ICDIM];  // [b, s, c]
__device__ float g_g2    [(size_t)BATCH * ICDIM * SLEN];   // [b, c, s]

// ============================================================================
// Vectorized SGEMM: C[b] = A @ B[b] (+ R[b]);  A [M,K] row-major, B [K,N] row-major.
// Requires M%128==0, N%128==0, K%8==0, all pointers 16B-aligned.
// 128x128 tile, BK=8, 256 threads, 8x8 per thread in 4+4 split layout.
// ============================================================================
template<bool ADD_RES>
__global__ __launch_bounds__(256) void sgemm_vec(
    const float* __restrict__ A, long sA,
    const float* __restrict__ B, long sB,
    const float* __restrict__ R, long sR,
    float* __restrict__ C, long sC,
    int M, int N, int K)
{
    const int b = blockIdx.z;
    A += (long)b * sA;
    B += (long)b * sB;
    C += (long)b * sC;
    if (ADD_RES) R += (long)b * sR;

    const int m0 = blockIdx.y * 128;
    const int n0 = blockIdx.x * 128;

    __shared__ float As[8][128];
    __shared__ float Bs[8][128];

    const int tid   = threadIdx.x;
    const int arow  = tid >> 1;          // 0..127
    const int acol4 = (tid & 1) * 4;     // 0 or 4
    const int brow  = tid >> 5;          // 0..7
    const int bcol4 = (tid & 31) * 4;    // 0..124

    const int cx4 = (tid & 15) * 4;      // col base
    const int cy4 = (tid >> 4) * 4;      // row base

    float acc[8][8];
    #pragma unroll
    for (int i = 0; i < 8; i++)
        #pragma unroll
        for (int j = 0; j < 8; j++) acc[i][j] = 0.f;

    for (int k0 = 0; k0 < K; k0 += 8) {
        float4 av = *reinterpret_cast<const float4*>(&A[(long)(m0 + arow) * K + k0 + acol4]);
        float4 bv = *reinterpret_cast<const float4*>(&B[(long)(k0 + brow) * N + n0 + bcol4]);
        As[acol4 + 0][arow] = av.x;
        As[acol4 + 1][arow] = av.y;
        As[acol4 + 2][arow] = av.z;
        As[acol4 + 3][arow] = av.w;
        *reinterpret_cast<float4*>(&Bs[brow][bcol4]) = bv;
        __syncthreads();

        #pragma unroll
        for (int k = 0; k < 8; k++) {
            float4 a0 = *reinterpret_cast<const float4*>(&As[k][cy4]);
            float4 a1 = *reinterpret_cast<const float4*>(&As[k][64 + cy4]);
            float4 b0 = *reinterpret_cast<const float4*>(&Bs[k][cx4]);
            float4 b1 = *reinterpret_cast<const float4*>(&Bs[k][64 + cx4]);
            float ra[8] = {a0.x, a0.y, a0.z, a0.w, a1.x, a1.y, a1.z, a1.w};
            float rb[8] = {b0.x, b0.y, b0.z, b0.w, b1.x, b1.y, b1.z, b1.w};
            #pragma unroll
            for (int i = 0; i < 8; i++)
                #pragma unroll
                for (int j = 0; j < 8; j++)
                    acc[i][j] = fmaf(ra[i], rb[j], acc[i][j]);
        }
        __syncthreads();
    }

    #pragma unroll
    for (int ih = 0; ih < 2; ih++) {
        #pragma unroll
        for (int i = 0; i < 4; i++) {
            long row = m0 + ih * 64 + cy4 + i;
            #pragma unroll
            for (int jh = 0; jh < 2; jh++) {
                long off = row * (long)N + n0 + jh * 64 + cx4;
                float4 v;
                v.x = acc[ih * 4 + i][jh * 4 + 0];
                v.y = acc[ih * 4 + i][jh * 4 + 1];
                v.z = acc[ih * 4 + i][jh * 4 + 2];
                v.w = acc[ih * 4 + i][jh * 4 + 3];
                if (ADD_RES) {
                    float4 r = *reinterpret_cast<const float4*>(&R[off]);
                    v.x += r.x; v.y += r.y; v.z += r.z; v.w += r.w;
                }
                *reinterpret_cast<float4*>(&C[off]) = v;
            }
        }
    }
}

// ============================================================================
// Guarded SGEMM (scalar loads): handles M not multiple of 128 and K not
// multiple of 8. Same tiling/compute as sgemm_vec. N must be multiple of 128.
// A is batched (stride sA).
// ============================================================================
__global__ __launch_bounds__(256) void sgemm_gen(
    const float* __restrict__ A, long sA,
    const float* __restrict__ B, long sB,
    float* __restrict__ C, long sC,
    int M, int N, int K)
{
    const int b = blockIdx.z;
    A += (long)b * sA;
    B += (long)b * sB;
    C += (long)b * sC;

    const int m0 = blockIdx.y * 128;
    const int n0 = blockIdx.x * 128;

    __shared__ float As[8][128];
    __shared__ float Bs[8][128];

    const int tid = threadIdx.x;
    const int cx4 = (tid & 15) * 4;
    const int cy4 = (tid >> 4) * 4;

    float acc[8][8];
    #pragma unroll
    for (int i = 0; i < 8; i++)
        #pragma unroll
        for (int j = 0; j < 8; j++) acc[i][j] = 0.f;

    for (int k0 = 0; k0 < K; k0 += 8) {
        #pragma unroll
        for (int l = 0; l < 4; l++) {
            int idx = tid + l * 256;
            int mrow = idx >> 3;
            int kk = idx & 7;
            float va = 0.f;
            if (m0 + mrow < M && k0 + kk < K)
                va = A[(long)(m0 + mrow) * K + k0 + kk];
            As[kk][mrow] = va;

            int bkk = idx >> 7;
            int ncol = idx & 127;
            float vb = 0.f;
            if (k0 + bkk < K)
                vb = B[(long)(k0 + bkk) * N + n0 + ncol];
            Bs[bkk][ncol] = vb;
        }
        __syncthreads();

        #pragma unroll
        for (int k = 0; k < 8; k++) {
            float4 a0 = *reinterpret_cast<const float4*>(&As[k][cy4]);
            float4 a1 = *reinterpret_cast<const float4*>(&As[k][64 + cy4]);
            float4 b0 = *reinterpret_cast<const float4*>(&Bs[k][cx4]);
            float4 b1 = *reinterpret_cast<const float4*>(&Bs[k][64 + cx4]);
            float ra[8] = {a0.x, a0.y, a0.z, a0.w, a1.x, a1.y, a1.z, a1.w};
            float rb[8] = {b0.x, b0.y, b0.z, b0.w, b1.x, b1.y, b1.z, b1.w};
            #pragma unroll
            for (int i = 0; i < 8; i++)
                #pragma unroll
                for (int j = 0; j < 8; j++)
                    acc[i][j] = fmaf(ra[i], rb[j], acc[i][j]);
        }
        __syncthreads();
    }

    #pragma unroll
    for (int ih = 0; ih < 2; ih++) {
        #pragma unroll
        for (int i = 0; i < 4; i++) {
            int row = m0 + ih * 64 + cy4 + i;
            if (row >= M) continue;
            #pragma unroll
            for (int jh = 0; jh < 2; jh++) {
                long off = (long)row * N + n0 + jh * 64 + cx4;
                #pragma unroll
                for (int j = 0; j < 4; j++)
                    C[off + j] = acc[ih * 4 + i][jh * 4 + j];
            }
        }
    }
}

// ============================================================================
// SPP adaptive max pooling over yconv [B, 512, 64, 64].
// PyTorch AdaptiveMaxPool2d bins: start = (i*64)//o, end = ceil((i+1)*64/o)
// (bins overlap for o=3,6). Pyramid o in {1,3,6,8}, S = 1+9+36+64 = 110.
// Channels 0..255 -> theta [b, s, c]; channels 256..511 -> g2 [b, c, s].
// ============================================================================
__global__ void spp_pool(const float* __restrict__ yconv,
                         float* __restrict__ theta,
                         float* __restrict__ g2)
{
    const int s = blockIdx.x;   // 0..109
    const int b = blockIdx.y;
    const int c = threadIdx.x;  // 0..511

    int o, base;
    if (s == 0)      { o = 1; base = 0; }
    else if (s < 10) { o = 3; base = 1; }
    else if (s < 46) { o = 6; base = 10; }
    else             { o = 8; base = 46; }
    const int li = s - base;
    const int i = li / o;
    const int j = li % o;
    const int h0 = (i * 64) / o;
    const int h1 = ((i + 1) * 64 + o - 1) / o;
    const int w0 = (j * 64) / o;
    const int w1 = ((j + 1) * 64 + o - 1) / o;

    const float* src = yconv + ((long)b * CDIM + c) * NPIX;
    float m = -3.4e38f;
    for (int h = h0; h < h1; h++) {
        const float* rowp = src + h * 64;
        for (int w = w0; w < w1; w++)
            m = fmaxf(m, rowp[w]);
    }

    if (c < ICDIM)
        theta[((long)b * SLEN + s) * ICDIM + c] = m;
    else
        g2[((long)b * ICDIM + (c - ICDIM)) * SLEN + s] = m;
}

// ============================================================================
// Softmax over the QUERY axis (n, 4096 elems) per (b, s) row; normalize
// logits[b, s, :] in place to probabilities.
// ============================================================================
__global__ void softmax_over_n(float* __restrict__ logits)
{
    const long row = blockIdx.x;                 // b*110 + s
    float* p = logits + row * (long)NPIX;
    const int tid = threadIdx.x;
    __shared__ float red[256];

    float m = -3.4e38f;
    for (int i = tid; i < NPIX; i += 256) m = fmaxf(m, p[i]);
    red[tid] = m;
    __syncthreads();
    for (int st = 128; st > 0; st >>= 1) {
        if (tid < st) red[tid] = fmaxf(red[tid], red[tid + st]);
        __syncthreads();
    }
    m = red[0];
    __syncthreads();

    float acc = 0.f;
    for (int i = tid; i < NPIX; i += 256) acc += expf(p[i] - m);
    red[tid] = acc;
    __syncthreads();
    for (int st = 128; st > 0; st >>= 1) {
        if (tid < st) red[tid] += red[tid + st];
        __syncthreads();
    }
    const float inv = 1.0f / red[0];

    for (int i = tid; i < NPIX; i += 256)
        p[i] = expf(p[i] - m) * inv;
}

// ============================================================================
// Launcher
// ============================================================================
extern "C" void kernel_launch(void* const* d_in, const int* in_sizes, int n_in,
                              void* d_out, int out_size)
{
    const float* x       = (const float*)d_in[0];  // [16, 512, 64, 64]
    const float* y       = (const float*)d_in[1];  // [16, 512, 64, 64]
    const float* w_phi   = (const float*)d_in[2];  // [256, 512]
    const float* w_theta = (const float*)d_in[3];  // [256, 512]
    const float* w_g     = (const float*)d_in[4];  // [256, 512]
    const float* w_mask  = (const float*)d_in[5];  // [512, 256]
    float* out = (float*)d_out;

    float *yconv, *xphi, *logits, *agg, *theta, *g2;
    cudaGetSymbolAddress((void**)&yconv,  g_yconv);
    cudaGetSymbolAddress((void**)&xphi,   g_xphi);
    cudaGetSymbolAddress((void**)&logits, g_logits);
    cudaGetSymbolAddress((void**)&agg,    g_agg);
    cudaGetSymbolAddress((void**)&theta,  g_theta);
    cudaGetSymbolAddress((void**)&g2,     g_g2);

    const long sXY   = (long)CDIM * NPIX;    // 512*4096 per-batch stride (x, y, out, yconv)
    const long sHalf = (long)ICDIM * NPIX;   // 256*4096 (xphi, agg)
    const long sLg   = (long)SLEN * NPIX;    // 110*4096 (logits)

    dim3 blk(256);

    // theta-conv and g-conv of y -> yconv halves   (M=256, N=4096, K=512 each)
    sgemm_vec<false><<<dim3(32, 2, BATCH), blk>>>(w_theta, 0, y, sXY, nullptr, 0,
                                                  yconv, sXY, 256, NPIX, 512);
    sgemm_vec<false><<<dim3(32, 2, BATCH), blk>>>(w_g, 0, y, sXY, nullptr, 0,
                                                  yconv + (long)ICDIM * NPIX, sXY, 256, NPIX, 512);
    // phi-conv of x -> xphi
    sgemm_vec<false><<<dim3(32, 2, BATCH), blk>>>(w_phi, 0, x, sXY, nullptr, 0,
                                                  xphi, sHalf, 256, NPIX, 512);
    // SPP pooling -> theta [b,s,c], g2 [b,c,s]
    spp_pool<<<dim3(SLEN, BATCH), 512>>>(yconv, theta, g2);

    // logits[b,s,n] = sum_c theta[b,s,c] * xphi[b,c,n]   (M=110, N=4096, K=256)
    sgemm_gen<<<dim3(32, 1, BATCH), blk>>>(theta, (long)SLEN * ICDIM, xphi, sHalf,
                                           logits, sLg, SLEN, NPIX, 256);
    // softmax over n (query axis), in place
    softmax_over_n<<<BATCH * SLEN, 256>>>(logits);

    // agg[b,c,n] = sum_s g2[b,c,s] * probs[b,s,n]   (M=256, N=4096, K=110)
    sgemm_gen<<<dim3(32, 2, BATCH), blk>>>(g2, (long)ICDIM * SLEN, logits, sLg,
                                           agg, sHalf, 256, NPIX, 110);
    // out = w_mask @ agg + x   (M=512, N=4096, K=256)
    sgemm_vec<true><<<dim3(32, 4, BATCH), blk>>>(w_mask, 0, agg, sHalf, x, sXY,
                                                 out, sXY, 512, NPIX, 256);
}